// round 12
// baseline (speedup 1.0000x reference)
#include <cuda_runtime.h>
#include <math.h>

#define BATCH 16
#define NC    2048
#define NT    2048
#define TG    2048
#define NBINS 128
#define RFAC  3.75f    // truncation tail ~ erfc(3.75/sqrt2) = 1.8e-4 << 1e-3 gate
#define EPS   1e-8f
#define LOG2E 1.4426950408889634f

__device__ __forceinline__ float ex2(float x) {
    float y;
    asm("ex2.approx.ftz.f32 %0, %1;" : "=f"(y) : "f"(x));
    return y;
}

// Fixed binning: xc is uniform in [0, 128). Bin width = 1.0. Clamped => safe.
__device__ __forceinline__ int bin_fix(float x) {
    int b = (int)floorf(x);
    return min(NBINS - 1, max(0, b));
}

// ---------------- scratch (no allocs allowed) ----------------
__device__ float    g_minmax[2];                 // [lower, upper] (final)
__device__ float    g_plo[BATCH], g_phi[BATCH];  // per-batch partials
__device__ unsigned g_done = 0;                  // completion counter (self-resetting)
__device__ int      g_starts[BATCH * (NBINS + 1)];
__device__ __align__(16) float2 g_sxy[BATCH * NC];  // (xc, yc) sorted by bin
__device__ __align__(16) float2 g_f[BATCH * TG];    // (f_mu, softplus(f_sigma))

// ---------------- K1: fused hist + scan + scatter + minmax ----------------
#define SNTH 1024
#define SPT  2   // NC / SNTH
__global__ __launch_bounds__(SNTH) void sort_kernel(
    const float* __restrict__ xc, const float* __restrict__ yc,
    const float* __restrict__ xt) {
    __shared__ int scnt[NBINS];
    __shared__ int scur[NBINS];
    __shared__ int wsum[32];
    __shared__ float slo[32], shi[32];
    int b = blockIdx.x, tid = threadIdx.x;
    int lane = tid & 31, w = tid >> 5;

    if (tid < NBINS) scnt[tid] = 0;
    __syncthreads();

    const float* xcb = xc + b * NC;
    const float* ycb = yc + b * NC;
    const float* xtb = xt + b * NT;

    // hoist ALL global loads into one MLP wave
    float xv[SPT], yv[SPT], tv[SPT];
    #pragma unroll
    for (int r = 0; r < SPT; r++) {
        int i = tid + r * SNTH;
        xv[r] = __ldg(&xcb[i]);
        yv[r] = __ldg(&ycb[i]);
        tv[r] = __ldg(&xtb[i]);
    }

    float lo = INFINITY, hi = -INFINITY;
    #pragma unroll
    for (int r = 0; r < SPT; r++) {
        lo = fminf(lo, fminf(xv[r], tv[r]));
        hi = fmaxf(hi, fmaxf(xv[r], tv[r]));
        atomicAdd(&scnt[bin_fix(xv[r])], 1);
    }
    #pragma unroll
    for (int off = 16; off; off >>= 1) {
        lo = fminf(lo, __shfl_xor_sync(0xffffffffu, lo, off));
        hi = fmaxf(hi, __shfl_xor_sync(0xffffffffu, hi, off));
    }
    if (lane == 0) { slo[w] = lo; shi[w] = hi; }
    __syncthreads();

    // exclusive scan of the 128 bin counts (threads >= 128 carry 0)
    int c = (tid < NBINS) ? scnt[tid] : 0;
    int v = c;
    #pragma unroll
    for (int off = 1; off < 32; off <<= 1) {
        int n = __shfl_up_sync(0xffffffffu, v, off);
        if (lane >= off) v += n;
    }
    if (lane == 31 && w < 4) wsum[w] = v;
    __syncthreads();
    if (tid == 0) {
        int run = 0;
        #pragma unroll
        for (int k = 0; k < 4; k++) { int t = wsum[k]; wsum[k] = run; run += t; }
        float flo = slo[0], fhi = shi[0];
        #pragma unroll
        for (int k = 1; k < 32; k++) { flo = fminf(flo, slo[k]); fhi = fmaxf(fhi, shi[k]); }
        g_plo[b] = flo; g_phi[b] = fhi;
    }
    __syncthreads();
    if (tid < NBINS) {
        int excl = v - c + wsum[w];
        scur[tid] = excl;
        g_starts[b * (NBINS + 1) + tid] = excl;
    }
    if (tid == 0) g_starts[b * (NBINS + 1) + NBINS] = NC;
    __syncthreads();

    // scatter from registers via smem cursors
    #pragma unroll
    for (int r = 0; r < SPT; r++) {
        int pos = atomicAdd(&scur[bin_fix(xv[r])], 1);
        g_sxy[b * NC + pos] = make_float2(xv[r], yv[r]);
    }

    // last block folds per-batch min/max partials into g_minmax
    __threadfence();
    if (tid == 0) {
        if (atomicAdd(&g_done, 1) == BATCH - 1) {
            __threadfence();
            volatile float* plo = g_plo;
            volatile float* phi = g_phi;
            float flo = INFINITY, fhi = -INFINITY;
            #pragma unroll
            for (int k = 0; k < BATCH; k++) {
                flo = fminf(flo, plo[k]); fhi = fmaxf(fhi, phi[k]);
            }
            g_minmax[0] = flo; g_minmax[1] = fhi;
            g_done = 0;
            __threadfence();
        }
    }
}

// ---------------- K2: fused psi + 4-layer conv chain ----------------
#define T_TILE 128
#define HALO   8
#define CW     (T_TILE + 2 * HALO)  // 144
#define CWP    152                  // padded row stride (floats), mult of 4
#define CNTH   256

// dynamic smem layout (floats), all offsets multiples of 4 (16B aligned)
#define OFF_S0  0
#define OFF_S1  (OFF_S0 + 3 * CWP)     // 456
#define OFF_S2  (OFF_S1 + 16 * CWP)    // 2888
#define OFF_W1  (OFF_S2 + 32 * CWP)    // 7752
#define OFF_W2  (OFF_W1 + 240)         // 7992
#define OFF_W3  (OFF_W2 + 2560)        // 10552
#define OFF_W4  (OFF_W3 + 2560)        // 13112
#define OFF_B1  (OFF_W4 + 160)         // 13272
#define OFF_B2  (OFF_B1 + 16)
#define OFF_B3  (OFF_B2 + 32)
#define OFF_B4  (OFF_B3 + 16)
#define SMEM_FLOATS (OFF_B4 + 4)
#define SMEM_BYTES  (SMEM_FLOATS * 4)

template <int NCO, int NCI, int LO>
__device__ __forceinline__ void conv_layer(const float* __restrict__ sin,
                                           float* __restrict__ sout,
                                           const float4* __restrict__ sw4,
                                           const float* __restrict__ sb,
                                           int p0, int tid) {
    constexpr int nv = CW - 2 * LO;         // 140 / 136 / 132 (all % 4 == 0)
    constexpr int ngp = nv / 4;
    constexpr int ncog = NCO / 4;
    constexpr int off = (LO - 2) & 3;       // 0 / 2 / 0

    for (int task = tid; task < ncog * ngp; task += CNTH) {
        int gp = task % ngp;
        int cog = task / ngp;
        int u0 = LO + gp * 4;
        int base = u0 - 2 - off;            // 16B aligned, >= 0

        float acc[4][4];
        #pragma unroll
        for (int q = 0; q < 4; q++)
            #pragma unroll
            for (int j = 0; j < 4; j++) acc[q][j] = 0.f;

        for (int ci = 0; ci < NCI; ci++) {
            const float4* sr = reinterpret_cast<const float4*>(sin + ci * CWP + base);
            float4 A = sr[0], B = sr[1], C = sr[2];
            float win[12] = {A.x, A.y, A.z, A.w, B.x, B.y, B.z, B.w,
                             C.x, C.y, C.z, C.w};
            #pragma unroll
            for (int k = 0; k < 5; k++) {
                float4 wv = sw4[(cog * NCI + ci) * 5 + k];
                #pragma unroll
                for (int j = 0; j < 4; j++) {
                    float xv = win[off + k + j];
                    acc[0][j] = fmaf(wv.x, xv, acc[0][j]);
                    acc[1][j] = fmaf(wv.y, xv, acc[1][j]);
                    acc[2][j] = fmaf(wv.z, xv, acc[2][j]);
                    acc[3][j] = fmaf(wv.w, xv, acc[3][j]);
                }
            }
        }
        #pragma unroll
        for (int q = 0; q < 4; q++) {
            int co = cog * 4 + q;
            float bias = sb[co];
            float v[4];
            #pragma unroll
            for (int j = 0; j < 4; j++) {
                int p = p0 + u0 + j;
                v[j] = (p >= 0 && p < TG) ? fmaxf(acc[q][j] + bias, 0.f) : 0.f;
            }
            float2* so = reinterpret_cast<float2*>(sout + co * CWP + u0);
            so[0] = make_float2(v[0], v[1]);
            so[1] = make_float2(v[2], v[3]);
        }
    }
}

__global__ __launch_bounds__(CNTH) void cnp_kernel(
    const float* __restrict__ pls, const float* __restrict__ pos_,
    const float* __restrict__ w1, const float* __restrict__ b1,
    const float* __restrict__ w2, const float* __restrict__ b2,
    const float* __restrict__ w3, const float* __restrict__ b3,
    const float* __restrict__ w4, const float* __restrict__ b4) {
    extern __shared__ float dsm[];
    float* s0 = dsm + OFF_S0;
    float* s1 = dsm + OFF_S1;
    float* s2 = dsm + OFF_S2;

    const int tiles = TG / T_TILE;  // 16
    int b = blockIdx.x / tiles;
    int tile = blockIdx.x % tiles;
    int p0 = tile * T_TILE - HALO;
    int tid = threadIdx.x;

    // stage weights, re-packed to [cog][ci][k][coq] so a thread's 4 co-weights
    // are a single broadcast LDS.128
    for (int i = tid; i < 240; i += CNTH) {   // w1: NCI=3 -> per-cog 60
        int co = i / 15, r = i % 15;
        dsm[OFF_W1 + (co >> 2) * 60 + r * 4 + (co & 3)] = __ldg(&w1[i]);
    }
    for (int i = tid; i < 2560; i += CNTH) {  // w2: NCI=16 -> per-cog 320
        int co = i / 80, r = i % 80;
        dsm[OFF_W2 + (co >> 2) * 320 + r * 4 + (co & 3)] = __ldg(&w2[i]);
    }
    for (int i = tid; i < 2560; i += CNTH) {  // w3: NCI=32 -> per-cog 640
        int co = i / 160, r = i % 160;
        dsm[OFF_W3 + (co >> 2) * 640 + r * 4 + (co & 3)] = __ldg(&w3[i]);
    }
    for (int i = tid; i < 160; i += CNTH)  dsm[OFF_W4 + i] = __ldg(&w4[i]);  // plain
    if (tid < 16) dsm[OFF_B1 + tid] = __ldg(&b1[tid]);
    if (tid < 32) dsm[OFF_B2 + tid] = __ldg(&b2[tid]);
    if (tid >= 32 && tid < 48) dsm[OFF_B3 + tid - 32] = __ldg(&b3[tid - 32]);
    if (tid >= 48 && tid < 50) dsm[OFF_B4 + tid - 48] = __ldg(&b4[tid - 48]);

    float lower = g_minmax[0], upper = g_minmax[1];
    float dt = (upper - lower) / (float)(TG - 1);

    // ---- psi phase: compute (t, h0, h1) for this block's CW positions ----
    // 4 sub-lanes per position; 576 tasks, multiple of 32 and round-aligned
    // at warp boundaries => full-warp shuffles are safe.
    {
        float ls = __ldg(pls), osv = __ldg(pos_);
        float nc2 = -0.5f * LOG2E / (ls * ls);
        float R = fabsf(ls) * RFAC;
        const int nb = b * (NBINS + 1);
        const float4* sp4 = reinterpret_cast<const float4*>(g_sxy + b * NC);

        for (int task = tid; task < CW * 4; task += CNTH) {
            int u = task >> 2, sub = task & 3;
            int p = p0 + u;
            bool in = (p >= 0 && p < TG);
            float t = lower + p * dt;
            float a00 = 0.f, a10 = 0.f, a01 = 0.f, a11 = 0.f;
            if (in) {
                int blo = min(NBINS - 1, max(0, (int)floorf(t - R)));
                int bhi = min(NBINS - 1, max(0, (int)floorf(t + R)));
                int s = g_starts[nb + blo];
                int e = g_starts[nb + bhi + 1];
                int j0 = (s >> 1) + sub;
                int j1 = (e - 1) >> 1;
                for (int j = j0; j <= j1; j += 4) {
                    float4 pt = __ldg(&sp4[j]);
                    float d0 = t - pt.x;
                    float d1 = t - pt.z;
                    float e0 = ex2(d0 * d0 * nc2);
                    float e1 = ex2(d1 * d1 * nc2);
                    a00 += e0; a10 = fmaf(e0, pt.y, a10);
                    a01 += e1; a11 = fmaf(e1, pt.w, a11);
                }
            }
            float a0 = a00 + a01, a1 = a10 + a11;
            #pragma unroll
            for (int off = 2; off; off >>= 1) {
                a0 += __shfl_xor_sync(0xffffffffu, a0, off);
                a1 += __shfl_xor_sync(0xffffffffu, a1, off);
            }
            if (sub == 0) {
                a0 *= osv; a1 *= osv;
                s0[0 * CWP + u] = in ? t : 0.f;
                s0[1 * CWP + u] = a0;                       // 0 if !in
                s0[2 * CWP + u] = in ? a1 / (a0 + EPS) : 0.f;
            }
        }
    }
    __syncthreads();

    conv_layer<16, 3, 2>(s0, s1, reinterpret_cast<const float4*>(dsm + OFF_W1),
                         dsm + OFF_B1, p0, tid);
    __syncthreads();
    conv_layer<32, 16, 4>(s1, s2, reinterpret_cast<const float4*>(dsm + OFF_W2),
                          dsm + OFF_B2, p0, tid);
    __syncthreads();
    conv_layer<16, 32, 6>(s2, s1, reinterpret_cast<const float4*>(dsm + OFF_W3),
                          dsm + OFF_B3, p0, tid);
    __syncthreads();

    // layer 4: 16 -> 2; one thread per position computes BOTH channels,
    // enabling a single float2 store (and float2 loads in rho).
    if (tid < T_TILE) {
        const float* sw4 = dsm + OFF_W4;
        const float* sb4 = dsm + OFF_B4;
        int u = HALO + tid;
        float acc0 = sb4[0], acc1 = sb4[1];
        #pragma unroll
        for (int ci = 0; ci < 16; ci++) {
            #pragma unroll
            for (int k = 0; k < 5; k++) {
                float xv = s1[ci * CWP + u - 2 + k];
                acc0 = fmaf(sw4[(0 * 16 + ci) * 5 + k], xv, acc0);
                acc1 = fmaf(sw4[(1 * 16 + ci) * 5 + k], xv, acc1);
            }
        }
        int p = p0 + u;                 // always in [0, TG)
        float sp = fmaxf(acc1, 0.f) + log1pf(__expf(-fabsf(acc1)));
        g_f[b * TG + p] = make_float2(acc0, sp);
    }
}

// ---------------- K3: rho stage — 8 lanes per target, float4 loads ----------------
__global__ void rho_kernel(const float* __restrict__ xt,
                           const float* __restrict__ pls,
                           const float* __restrict__ pos_,
                           float* __restrict__ out) {
    int g = (blockIdx.x * blockDim.x + threadIdx.x) >> 3;   // group id = target
    int sub = threadIdx.x & 7;
    if (g >= BATCH * NT) return;
    int b = g >> 11;

    float lower = g_minmax[0];
    float dt = (g_minmax[1] - lower) / (float)(TG - 1);
    float inv_dt = 1.f / dt;
    float x = __ldg(&xt[g]);
    float ls = __ldg(pls), osv = __ldg(pos_);
    float nc2 = -0.5f * LOG2E / (ls * ls);
    float R = fabsf(ls) * RFAC;

    int ilo = max(0, (int)ceilf((x - R - lower) * inv_dt));
    int ihi = min(TG - 1, (int)floorf((x + R - lower) * inv_dt));

    // pair-granular window; extra grid points are exact contributions and
    // stay in-bounds (ihi even => ihi <= TG-2 => pair covers <= TG-1).
    int j0 = (ilo >> 1) + sub;
    int j1 = ihi >> 1;
    const float4* f4 = reinterpret_cast<const float4*>(g_f + b * TG);
    float mu0 = 0.f, sg0 = 0.f, mu1 = 0.f, sg1 = 0.f;
    float d0 = x - (lower + (float)(2 * j0) * dt);
    float step16 = 16.f * dt;
    for (int j = j0; j <= j1; j += 8) {
        float4 v = __ldg(&f4[j]);
        float d1 = d0 - dt;
        float e0 = ex2(d0 * d0 * nc2);
        float e1 = ex2(d1 * d1 * nc2);
        mu0 = fmaf(e0, v.x, mu0); sg0 = fmaf(e0, v.y, sg0);
        mu1 = fmaf(e1, v.z, mu1); sg1 = fmaf(e1, v.w, sg1);
        d0 -= step16;
    }
    float mu = mu0 + mu1, sg = sg0 + sg1;
    #pragma unroll
    for (int off = 4; off; off >>= 1) {
        mu += __shfl_xor_sync(0xffffffffu, mu, off);
        sg += __shfl_xor_sync(0xffffffffu, sg, off);
    }
    if (sub == 0) {
        reinterpret_cast<float2*>(out)[g] = make_float2(mu * osv, sg * osv);
    }
}

// ---------------- launch ----------------
extern "C" void kernel_launch(void* const* d_in, const int* in_sizes, int n_in,
                              void* d_out, int out_size) {
    const float* xc = (const float*)d_in[0];
    const float* yc = (const float*)d_in[1];
    const float* xt = (const float*)d_in[2];
    const float* ls_psi = (const float*)d_in[3];
    const float* os_psi = (const float*)d_in[4];
    const float* ls_rho = (const float*)d_in[5];
    const float* os_rho = (const float*)d_in[6];
    const float* w1 = (const float*)d_in[7];
    const float* b1 = (const float*)d_in[8];
    const float* w2 = (const float*)d_in[9];
    const float* b2 = (const float*)d_in[10];
    const float* w3 = (const float*)d_in[11];
    const float* b3 = (const float*)d_in[12];
    const float* w4 = (const float*)d_in[13];
    const float* b4 = (const float*)d_in[14];
    float* out = (float*)d_out;

    cudaFuncSetAttribute(cnp_kernel,
                         cudaFuncAttributeMaxDynamicSharedMemorySize, SMEM_BYTES);

    sort_kernel<<<BATCH, SNTH>>>(xc, yc, xt);
    cnp_kernel<<<BATCH * (TG / T_TILE), CNTH, SMEM_BYTES>>>(
        ls_psi, os_psi, w1, b1, w2, b2, w3, b3, w4, b4);
    rho_kernel<<<(BATCH * NT) * 8 / 256, 256>>>(xt, ls_rho, os_rho, out);
}